// round 15
// baseline (speedup 1.0000x reference)
#include <cuda_runtime.h>
#include <cstdint>

// Fused GNN forward. R7 config (2 CTAs/SM x 128 threads, BPW=4, plain FMA,
// full register budget) + cp.async next-group prefetch overlapped with the
// hidden/decoder phase (fint in its own buffer so the states buffer is dead
// after the encoder).

namespace {
constexpr int NSTATES = 16;
constexpr int SSIZE   = 32;
constexpr int ENCD    = 64;
constexpr int HIDD    = 128;
constexpr int OUTD    = 8;
constexpr int BPW     = 4;
constexpr int NWARP   = 4;
constexpr int THREADS = NWARP * 32;            // 128
constexpr unsigned FULL = 0xffffffffu;

constexpr int WENC_F  = 16 * 32 * 4;           // 2048 floats (8 KB)   [s2][lane] float4
constexpr int WF_F    = HIDD * 32 * 4;         // 16384 floats (64 KB) [i][lane] float4
constexpr int STATE_F = BPW * NSTATES * SSIZE; // 2048 floats (8 KB) per warp
constexpr int FINT_F  = HIDD * 4;              // 512 floats (2 KB) per warp
constexpr int SMEM_FLOATS = WENC_F + WF_F + NWARP * (STATE_F + FINT_F);
constexpr int SMEM_BYTES  = SMEM_FLOATS * 4;   // 114688 B = 112 KB per CTA
}

__device__ __forceinline__ void cp_async16(unsigned int dst, const void* src) {
    asm volatile("cp.async.cg.shared.global [%0], [%1], 16;\n" :: "r"(dst), "l"(src));
}
__device__ __forceinline__ void cp_async_commit() {
    asm volatile("cp.async.commit_group;\n" ::: "memory");
}
__device__ __forceinline__ void cp_async_wait0() {
    asm volatile("cp.async.wait_group 0;\n" ::: "memory");
}

__global__ __launch_bounds__(THREADS, 2)
void gnn_fused(const float* __restrict__ obs,
               const float* __restrict__ W_enc, const float* __restrict__ b_enc,
               const float* __restrict__ W_f,   const float* __restrict__ b_f,
               const float* __restrict__ W_dec, const float* __restrict__ b_dec,
               float* __restrict__ out, int B)
{
    extern __shared__ float smem[];
    float4* Wenc2    = reinterpret_cast<float4*>(smem);           // [s2=16][lane]
    float4* Wfp      = reinterpret_cast<float4*>(smem + WENC_F);  // [i=128][lane]
    float*  st_all   = smem + WENC_F + WF_F;                      // [warp][2048]
    float*  fint_all = st_all + NWARP * STATE_F;                  // [warp][512]

    const int tid = threadIdx.x;

    // ---- stage weights once per CTA ----
    for (int idx = tid; idx < 16 * 32; idx += THREADS) {
        int s2 = idx >> 5, l = idx & 31;
        Wenc2[idx] = make_float4(W_enc[(2 * s2)     * ENCD + l], W_enc[(2 * s2)     * ENCD + l + 32],
                                 W_enc[(2 * s2 + 1) * ENCD + l], W_enc[(2 * s2 + 1) * ENCD + l + 32]);
    }
    for (int idx = tid; idx < HIDD * 32; idx += THREADS) {
        int i = idx >> 5, l = idx & 31;
        Wfp[idx] = make_float4(W_f[i * HIDD + l],      W_f[i * HIDD + l + 32],
                               W_f[i * HIDD + l + 64], W_f[i * HIDD + l + 96]);
    }
    __syncthreads();

    const int lane = tid & 31;
    const int warp = tid >> 5;

    float* stw = st_all + warp * STATE_F;
    const unsigned int stw_addr = (unsigned int)__cvta_generic_to_shared(stw);
    float4* fint = reinterpret_cast<float4*>(fint_all + warp * FINT_F);  // [i=128] {j0..j3}

    // per-lane biases / decoder weights
    const float be0 = __ldg(b_enc + lane);
    const float be1 = __ldg(b_enc + lane + 32);
    const float bf0 = __ldg(b_f + lane);
    const float bf1 = __ldg(b_f + lane + 32);
    const float bf2 = __ldg(b_f + lane + 64);
    const float bf3 = __ldg(b_f + lane + 96);
    float wd[4][OUTD];
    #pragma unroll
    for (int m = 0; m < 4; m++)
        #pragma unroll
        for (int o = 0; o < OUTD; o++)
            wd[m][o] = __ldg(W_dec + (lane + 32 * m) * OUTD + o);
    float bd[OUTD];
    #pragma unroll
    for (int o = 0; o < OUTD; o++) bd[o] = __ldg(b_dec + o);

    const int groups  = B / BPW;
    const int gw0     = blockIdx.x * NWARP + warp;
    const int gstride = gridDim.x * NWARP;

    // ---- prologue: prefetch first group's states ----
    if (gw0 < groups) {
        const char* src = reinterpret_cast<const char*>(obs) + (long long)gw0 * (STATE_F * 4);
        #pragma unroll
        for (int k = 0; k < 16; k++) {
            int c = k * 32 + lane;
            cp_async16(stw_addr + c * 16, src + c * 16);
        }
        cp_async_commit();
    }

    for (int g = gw0; g < groups; g += gstride) {
        cp_async_wait0();
        __syncwarp();

        // ---- encoder: rows n=0..15 with running validity, warp-uniform break ----
        float fin[4][BPW];     // k0=agent lo, k1=agent hi, k2=agg lo, k3=agg hi
        float g0[BPW], g1[BPW];
        bool  ok[BPW];
        int   cnt[BPW];
        #pragma unroll
        for (int j = 0; j < BPW; j++) { g0[j] = 0.0f; g1[j] = 0.0f; ok[j] = true; cnt[j] = 0; }

        for (int n = 0; n < NSTATES; n++) {
            if (n >= 1) {
                bool any = false;
                #pragma unroll
                for (int j = 0; j < BPW; j++) {
                    float fl = stw[(j * NSTATES + n) * SSIZE];  // broadcast scalar LDS
                    ok[j] = ok[j] && (fl == 1.0f);
                    any = any || ok[j];
                    cnt[j] += ok[j] ? 1 : 0;
                }
                if (!any) break;   // warp-uniform
            }

            float e0[BPW], e1[BPW];
            #pragma unroll
            for (int j = 0; j < BPW; j++) { e0[j] = be0; e1[j] = be1; }
            #pragma unroll
            for (int s4 = 0; s4 < 8; s4++) {
                float4 w0 = Wenc2[(2 * s4)     * 32 + lane];
                float4 w1 = Wenc2[(2 * s4 + 1) * 32 + lane];
                #pragma unroll
                for (int j = 0; j < BPW; j++) {
                    const float4 a = *reinterpret_cast<const float4*>(&stw[(j * NSTATES + n) * SSIZE + s4 * 4]);
                    e0[j] = fmaf(a.x, w0.x, e0[j]); e1[j] = fmaf(a.x, w0.y, e1[j]);
                    e0[j] = fmaf(a.y, w0.z, e0[j]); e1[j] = fmaf(a.y, w0.w, e1[j]);
                    e0[j] = fmaf(a.z, w1.x, e0[j]); e1[j] = fmaf(a.z, w1.y, e1[j]);
                    e0[j] = fmaf(a.w, w1.z, e0[j]); e1[j] = fmaf(a.w, w1.w, e1[j]);
                }
            }

            if (n == 0) {
                #pragma unroll
                for (int j = 0; j < BPW; j++) {
                    fin[0][j] = fmaxf(e0[j], 0.0f);
                    fin[1][j] = fmaxf(e1[j], 0.0f);
                }
            } else {
                #pragma unroll
                for (int j = 0; j < BPW; j++) {
                    if (ok[j]) {
                        g0[j] += fmaxf(e0[j], 0.0f);
                        g1[j] += fmaxf(e1[j], 0.0f);
                    }
                }
            }
        }
        #pragma unroll
        for (int j = 0; j < BPW; j++) {
            float inv = 1.0f / fmaxf((float)cnt[j], 1.0f);
            fin[2][j] = g0[j] * inv;
            fin[3][j] = g1[j] * inv;
        }

        // ---- states buffer now dead: prefetch next group behind compute ----
        __syncwarp();
        {
            int gn = g + gstride;
            if (gn < groups) {
                const char* src = reinterpret_cast<const char*>(obs) + (long long)gn * (STATE_F * 4);
                #pragma unroll
                for (int k = 0; k < 16; k++) {
                    int c = k * 32 + lane;
                    cp_async16(stw_addr + c * 16, src + c * 16);
                }
                cp_async_commit();
            }
        }

        // ---- store f_in transposed into its own buffer ----
        #pragma unroll
        for (int k = 0; k < 4; k++)
            fint[k * 32 + lane] = make_float4(fin[k][0], fin[k][1], fin[k][2], fin[k][3]);
        __syncwarp();

        // ---- hidden 128x128: per i, 1 bcast LDS.128 + 1 weight LDS.128, 16 FMA ----
        float h[BPW][4];
        #pragma unroll
        for (int j = 0; j < BPW; j++) { h[j][0] = bf0; h[j][1] = bf1; h[j][2] = bf2; h[j][3] = bf3; }
        #pragma unroll 8
        for (int i = 0; i < HIDD; i++) {
            float4 a = fint[i];                 // broadcast: activations for j=0..3
            float4 w = Wfp[i * 32 + lane];
            h[0][0] = fmaf(a.x, w.x, h[0][0]); h[0][1] = fmaf(a.x, w.y, h[0][1]);
            h[0][2] = fmaf(a.x, w.z, h[0][2]); h[0][3] = fmaf(a.x, w.w, h[0][3]);
            h[1][0] = fmaf(a.y, w.x, h[1][0]); h[1][1] = fmaf(a.y, w.y, h[1][1]);
            h[1][2] = fmaf(a.y, w.z, h[1][2]); h[1][3] = fmaf(a.y, w.w, h[1][3]);
            h[2][0] = fmaf(a.z, w.x, h[2][0]); h[2][1] = fmaf(a.z, w.y, h[2][1]);
            h[2][2] = fmaf(a.z, w.z, h[2][2]); h[2][3] = fmaf(a.z, w.w, h[2][3]);
            h[3][0] = fmaf(a.w, w.x, h[3][0]); h[3][1] = fmaf(a.w, w.y, h[3][1]);
            h[3][2] = fmaf(a.w, w.z, h[3][2]); h[3][3] = fmaf(a.w, w.w, h[3][3]);
        }

        // ---- decoder + warp reduce + store ----
        const int b0 = g * BPW;
        #pragma unroll
        for (int j = 0; j < BPW; j++) {
            float h0 = fmaxf(h[j][0], 0.0f);
            float h1 = fmaxf(h[j][1], 0.0f);
            float h2 = fmaxf(h[j][2], 0.0f);
            float h3 = fmaxf(h[j][3], 0.0f);
            float p[OUTD];
            #pragma unroll
            for (int o = 0; o < OUTD; o++)
                p[o] = fmaf(h0, wd[0][o], fmaf(h1, wd[1][o], fmaf(h2, wd[2][o], h3 * wd[3][o])));
            #pragma unroll
            for (int off = 16; off > 0; off >>= 1)
                #pragma unroll
                for (int o = 0; o < OUTD; o++)
                    p[o] += __shfl_down_sync(FULL, p[o], off);
            if (lane == 0) {
                float* po = out + (long long)(b0 + j) * OUTD;
                *reinterpret_cast<float4*>(po)     = make_float4(p[0] + bd[0], p[1] + bd[1],
                                                                p[2] + bd[2], p[3] + bd[3]);
                *reinterpret_cast<float4*>(po + 4) = make_float4(p[4] + bd[4], p[5] + bd[5],
                                                                p[6] + bd[6], p[7] + bd[7]);
            }
        }
    }
}

extern "C" void kernel_launch(void* const* d_in, const int* in_sizes, int n_in,
                              void* d_out, int out_size)
{
    const float* obs   = (const float*)d_in[0];
    const float* W_enc = (const float*)d_in[1];
    const float* b_enc = (const float*)d_in[2];
    const float* W_f   = (const float*)d_in[3];
    const float* b_f   = (const float*)d_in[4];
    const float* W_dec = (const float*)d_in[5];
    const float* b_dec = (const float*)d_in[6];
    float* out = (float*)d_out;

    const int B = in_sizes[0] / (NSTATES * SSIZE);

    static bool attr_done = false;
    if (!attr_done) {
        cudaFuncSetAttribute(gnn_fused, cudaFuncAttributeMaxDynamicSharedMemorySize, SMEM_BYTES);
        attr_done = true;
    }

    const int grid = 296;  // 148 SMs x 2 CTAs (112 KB smem each), 4 warps per CTA
    gnn_fused<<<grid, THREADS, SMEM_BYTES>>>(obs, W_enc, b_enc, W_f, b_f, W_dec, b_dec, out, B);
}

// round 16
// speedup vs baseline: 1.1537x; 1.1537x over previous
#include <cuda_runtime.h>
#include <cstdint>

// Fused GNN forward. R7 structure exactly (ballot-precomputed valid counts,
// separate agent row, uniform-break neighbor loop) + cp.async next-group
// prefetch overlapped with hidden/decoder (fint in its own buffer).

namespace {
constexpr int NSTATES = 16;
constexpr int SSIZE   = 32;
constexpr int ENCD    = 64;
constexpr int HIDD    = 128;
constexpr int OUTD    = 8;
constexpr int BPW     = 4;
constexpr int NWARP   = 4;
constexpr int THREADS = NWARP * 32;            // 128
constexpr unsigned FULL = 0xffffffffu;

constexpr int WENC_F  = 16 * 32 * 4;           // 2048 floats (8 KB)   [s2][lane] float4
constexpr int WF_F    = HIDD * 32 * 4;         // 16384 floats (64 KB) [i][lane] float4
constexpr int STATE_F = BPW * NSTATES * SSIZE; // 2048 floats (8 KB) per warp
constexpr int FINT_F  = HIDD * 4;              // 512 floats (2 KB) per warp
constexpr int SMEM_FLOATS = WENC_F + WF_F + NWARP * (STATE_F + FINT_F);
constexpr int SMEM_BYTES  = SMEM_FLOATS * 4;   // 114688 B = 112 KB per CTA
}

__device__ __forceinline__ void cp_async16(unsigned int dst, const void* src) {
    asm volatile("cp.async.cg.shared.global [%0], [%1], 16;\n" :: "r"(dst), "l"(src));
}
__device__ __forceinline__ void cp_async_commit() {
    asm volatile("cp.async.commit_group;\n" ::: "memory");
}
__device__ __forceinline__ void cp_async_wait0() {
    asm volatile("cp.async.wait_group 0;\n" ::: "memory");
}

__global__ __launch_bounds__(THREADS, 2)
void gnn_fused(const float* __restrict__ obs,
               const float* __restrict__ W_enc, const float* __restrict__ b_enc,
               const float* __restrict__ W_f,   const float* __restrict__ b_f,
               const float* __restrict__ W_dec, const float* __restrict__ b_dec,
               float* __restrict__ out, int B)
{
    extern __shared__ float smem[];
    float4* Wenc2    = reinterpret_cast<float4*>(smem);           // [s2=16][lane]
    float4* Wfp      = reinterpret_cast<float4*>(smem + WENC_F);  // [i=128][lane]
    float*  st_all   = smem + WENC_F + WF_F;                      // [warp][2048]
    float*  fint_all = st_all + NWARP * STATE_F;                  // [warp][512]

    const int tid = threadIdx.x;

    // ---- stage weights once per CTA ----
    for (int idx = tid; idx < 16 * 32; idx += THREADS) {
        int s2 = idx >> 5, l = idx & 31;
        Wenc2[idx] = make_float4(W_enc[(2 * s2)     * ENCD + l], W_enc[(2 * s2)     * ENCD + l + 32],
                                 W_enc[(2 * s2 + 1) * ENCD + l], W_enc[(2 * s2 + 1) * ENCD + l + 32]);
    }
    for (int idx = tid; idx < HIDD * 32; idx += THREADS) {
        int i = idx >> 5, l = idx & 31;
        Wfp[idx] = make_float4(W_f[i * HIDD + l],      W_f[i * HIDD + l + 32],
                               W_f[i * HIDD + l + 64], W_f[i * HIDD + l + 96]);
    }
    __syncthreads();

    const int lane = tid & 31;
    const int warp = tid >> 5;

    float* stw = st_all + warp * STATE_F;
    const unsigned int stw_addr = (unsigned int)__cvta_generic_to_shared(stw);
    float4* fint = reinterpret_cast<float4*>(fint_all + warp * FINT_F);  // [i=128] {j0..j3}

    // per-lane biases / decoder weights
    const float be0 = __ldg(b_enc + lane);
    const float be1 = __ldg(b_enc + lane + 32);
    const float bf0 = __ldg(b_f + lane);
    const float bf1 = __ldg(b_f + lane + 32);
    const float bf2 = __ldg(b_f + lane + 64);
    const float bf3 = __ldg(b_f + lane + 96);
    float wd[4][OUTD];
    #pragma unroll
    for (int m = 0; m < 4; m++)
        #pragma unroll
        for (int o = 0; o < OUTD; o++)
            wd[m][o] = __ldg(W_dec + (lane + 32 * m) * OUTD + o);
    float bd[OUTD];
    #pragma unroll
    for (int o = 0; o < OUTD; o++) bd[o] = __ldg(b_dec + o);

    const int groups  = B / BPW;
    const int gw0     = blockIdx.x * NWARP + warp;
    const int gstride = gridDim.x * NWARP;

    // ---- prologue: prefetch first group's states ----
    if (gw0 < groups) {
        const char* src = reinterpret_cast<const char*>(obs) + (long long)gw0 * (STATE_F * 4);
        #pragma unroll
        for (int k = 0; k < 16; k++) {
            int c = k * 32 + lane;
            cp_async16(stw_addr + c * 16, src + c * 16);
        }
        cp_async_commit();
    }

    for (int g = gw0; g < groups; g += gstride) {
        cp_async_wait0();
        __syncwarp();

        // ---- flags -> valid-prefix counts via ballot (R7 structure) ----
        float fA = stw[(((lane >> 4)    ) * NSTATES + (lane & 15)) * SSIZE];
        float fB = stw[(((lane >> 4) + 2) * NSTATES + (lane & 15)) * SSIZE];
        unsigned m0 = __ballot_sync(FULL, fA == 1.0f);
        unsigned m1 = __ballot_sync(FULL, fB == 1.0f);
        int nv[BPW];
        int maxnv = 0;
        #pragma unroll
        for (int j = 0; j < BPW; j++) {
            unsigned m = (j < 2) ? m0 : m1;
            unsigned t = (~(m >> ((j & 1) * 16 + 1))) & 0x7FFFu;
            nv[j] = t ? (__ffs((int)t) - 1) : 15;
            maxnv = nv[j] > maxnv ? nv[j] : maxnv;
        }

        // ---- encoder ----
        float fin[4][BPW];  // k0=agent lo, k1=agent hi, k2=agg lo, k3=agg hi

        // agent row (n = 0)
        {
            float e0[BPW], e1[BPW];
            #pragma unroll
            for (int j = 0; j < BPW; j++) { e0[j] = be0; e1[j] = be1; }
            #pragma unroll
            for (int s4 = 0; s4 < 8; s4++) {
                float4 w0 = Wenc2[(2 * s4)     * 32 + lane];
                float4 w1 = Wenc2[(2 * s4 + 1) * 32 + lane];
                #pragma unroll
                for (int j = 0; j < BPW; j++) {
                    float4 a = *reinterpret_cast<const float4*>(&stw[(j * NSTATES + 0) * SSIZE + s4 * 4]);
                    e0[j] = fmaf(a.x, w0.x, e0[j]); e1[j] = fmaf(a.x, w0.y, e1[j]);
                    e0[j] = fmaf(a.y, w0.z, e0[j]); e1[j] = fmaf(a.y, w0.w, e1[j]);
                    e0[j] = fmaf(a.z, w1.x, e0[j]); e1[j] = fmaf(a.z, w1.y, e1[j]);
                    e0[j] = fmaf(a.w, w1.z, e0[j]); e1[j] = fmaf(a.w, w1.w, e1[j]);
                }
            }
            #pragma unroll
            for (int j = 0; j < BPW; j++) {
                fin[0][j] = fmaxf(e0[j], 0.0f);
                fin[1][j] = fmaxf(e1[j], 0.0f);
            }
        }

        // neighbor rows 1..maxnv (warp-uniform early exit)
        {
            float g0[BPW], g1[BPW];
            #pragma unroll
            for (int j = 0; j < BPW; j++) { g0[j] = 0.0f; g1[j] = 0.0f; }
            for (int n = 1; n <= maxnv; n++) {
                float e0[BPW], e1[BPW];
                #pragma unroll
                for (int j = 0; j < BPW; j++) { e0[j] = be0; e1[j] = be1; }
                #pragma unroll
                for (int s4 = 0; s4 < 8; s4++) {
                    float4 w0 = Wenc2[(2 * s4)     * 32 + lane];
                    float4 w1 = Wenc2[(2 * s4 + 1) * 32 + lane];
                    #pragma unroll
                    for (int j = 0; j < BPW; j++) {
                        float4 a = *reinterpret_cast<const float4*>(&stw[(j * NSTATES + n) * SSIZE + s4 * 4]);
                        e0[j] = fmaf(a.x, w0.x, e0[j]); e1[j] = fmaf(a.x, w0.y, e1[j]);
                        e0[j] = fmaf(a.y, w0.z, e0[j]); e1[j] = fmaf(a.y, w0.w, e1[j]);
                        e0[j] = fmaf(a.z, w1.x, e0[j]); e1[j] = fmaf(a.z, w1.y, e1[j]);
                        e0[j] = fmaf(a.w, w1.z, e0[j]); e1[j] = fmaf(a.w, w1.w, e1[j]);
                    }
                }
                #pragma unroll
                for (int j = 0; j < BPW; j++) {
                    if (n <= nv[j]) {
                        g0[j] += fmaxf(e0[j], 0.0f);
                        g1[j] += fmaxf(e1[j], 0.0f);
                    }
                }
            }
            #pragma unroll
            for (int j = 0; j < BPW; j++) {
                float inv = 1.0f / fmaxf((float)nv[j], 1.0f);
                fin[2][j] = g0[j] * inv;
                fin[3][j] = g1[j] * inv;
            }
        }

        // ---- states buffer now dead: prefetch next group behind hidden/decoder ----
        __syncwarp();
        {
            int gn = g + gstride;
            if (gn < groups) {
                const char* src = reinterpret_cast<const char*>(obs) + (long long)gn * (STATE_F * 4);
                #pragma unroll
                for (int k = 0; k < 16; k++) {
                    int c = k * 32 + lane;
                    cp_async16(stw_addr + c * 16, src + c * 16);
                }
                cp_async_commit();
            }
        }

        // ---- store f_in transposed into its own buffer ----
        #pragma unroll
        for (int k = 0; k < 4; k++)
            fint[k * 32 + lane] = make_float4(fin[k][0], fin[k][1], fin[k][2], fin[k][3]);
        __syncwarp();

        // ---- hidden 128x128: per i, 1 bcast LDS.128 + 1 weight LDS.128, 16 FMA ----
        float h[BPW][4];
        #pragma unroll
        for (int j = 0; j < BPW; j++) { h[j][0] = bf0; h[j][1] = bf1; h[j][2] = bf2; h[j][3] = bf3; }
        #pragma unroll 8
        for (int i = 0; i < HIDD; i++) {
            float4 a = fint[i];                 // broadcast: activations for j=0..3
            float4 w = Wfp[i * 32 + lane];
            h[0][0] = fmaf(a.x, w.x, h[0][0]); h[0][1] = fmaf(a.x, w.y, h[0][1]);
            h[0][2] = fmaf(a.x, w.z, h[0][2]); h[0][3] = fmaf(a.x, w.w, h[0][3]);
            h[1][0] = fmaf(a.y, w.x, h[1][0]); h[1][1] = fmaf(a.y, w.y, h[1][1]);
            h[1][2] = fmaf(a.y, w.z, h[1][2]); h[1][3] = fmaf(a.y, w.w, h[1][3]);
            h[2][0] = fmaf(a.z, w.x, h[2][0]); h[2][1] = fmaf(a.z, w.y, h[2][1]);
            h[2][2] = fmaf(a.z, w.z, h[2][2]); h[2][3] = fmaf(a.z, w.w, h[2][3]);
            h[3][0] = fmaf(a.w, w.x, h[3][0]); h[3][1] = fmaf(a.w, w.y, h[3][1]);
            h[3][2] = fmaf(a.w, w.z, h[3][2]); h[3][3] = fmaf(a.w, w.w, h[3][3]);
        }

        // ---- decoder + warp reduce + store ----
        const int b0 = g * BPW;
        #pragma unroll
        for (int j = 0; j < BPW; j++) {
            float h0 = fmaxf(h[j][0], 0.0f);
            float h1 = fmaxf(h[j][1], 0.0f);
            float h2 = fmaxf(h[j][2], 0.0f);
            float h3 = fmaxf(h[j][3], 0.0f);
            float p[OUTD];
            #pragma unroll
            for (int o = 0; o < OUTD; o++)
                p[o] = fmaf(h0, wd[0][o], fmaf(h1, wd[1][o], fmaf(h2, wd[2][o], h3 * wd[3][o])));
            #pragma unroll
            for (int off = 16; off > 0; off >>= 1)
                #pragma unroll
                for (int o = 0; o < OUTD; o++)
                    p[o] += __shfl_down_sync(FULL, p[o], off);
            if (lane == 0) {
                float* po = out + (long long)(b0 + j) * OUTD;
                *reinterpret_cast<float4*>(po)     = make_float4(p[0] + bd[0], p[1] + bd[1],
                                                                p[2] + bd[2], p[3] + bd[3]);
                *reinterpret_cast<float4*>(po + 4) = make_float4(p[4] + bd[4], p[5] + bd[5],
                                                                p[6] + bd[6], p[7] + bd[7]);
            }
        }
    }
}

extern "C" void kernel_launch(void* const* d_in, const int* in_sizes, int n_in,
                              void* d_out, int out_size)
{
    const float* obs   = (const float*)d_in[0];
    const float* W_enc = (const float*)d_in[1];
    const float* b_enc = (const float*)d_in[2];
    const float* W_f   = (const float*)d_in[3];
    const float* b_f   = (const float*)d_in[4];
    const float* W_dec = (const float*)d_in[5];
    const float* b_dec = (const float*)d_in[6];
    float* out = (float*)d_out;

    const int B = in_sizes[0] / (NSTATES * SSIZE);

    static bool attr_done = false;
    if (!attr_done) {
        cudaFuncSetAttribute(gnn_fused, cudaFuncAttributeMaxDynamicSharedMemorySize, SMEM_BYTES);
        attr_done = true;
    }

    const int grid = 296;  // 148 SMs x 2 CTAs (112 KB smem each), 4 warps per CTA
    gnn_fused<<<grid, THREADS, SMEM_BYTES>>>(obs, W_enc, b_enc, W_f, b_f, W_dec, b_dec, out, B);
}